// round 4
// baseline (speedup 1.0000x reference)
#include <cuda_runtime.h>

#define FULL_MASK 0xffffffffu

// ---------- packed f32x2 + fast-math helpers ----------
__device__ __forceinline__ float2 ffma2(float2 a, float2 b, float2 c) {
    unsigned long long au = *reinterpret_cast<unsigned long long*>(&a);
    unsigned long long bu = *reinterpret_cast<unsigned long long*>(&b);
    unsigned long long cu = *reinterpret_cast<unsigned long long*>(&c);
    unsigned long long du;
    asm("fma.rn.f32x2 %0, %1, %2, %3;" : "=l"(du) : "l"(au), "l"(bu), "l"(cu));
    return *reinterpret_cast<float2*>(&du);
}
__device__ __forceinline__ float2 fadd2(float2 a, float2 b) {
    unsigned long long au = *reinterpret_cast<unsigned long long*>(&a);
    unsigned long long bu = *reinterpret_cast<unsigned long long*>(&b);
    unsigned long long du;
    asm("add.rn.f32x2 %0, %1, %2;" : "=l"(du) : "l"(au), "l"(bu));
    return *reinterpret_cast<float2*>(&du);
}
__device__ __forceinline__ float ex2a(float x) {
    float r; asm("ex2.approx.f32 %0, %1;" : "=f"(r) : "f"(x)); return r;
}
__device__ __forceinline__ float rcpa(float x) {
    float r; asm("rcp.approx.f32 %0, %1;" : "=f"(r) : "f"(x)); return r;
}

// H=32, 4H=128, I=1, T=512, B=8192.
//
// One warp handles FOUR batch elements. The 128 W_hh weight registers are
// shared across all four; each batch adds only its recurrence state. Four
// independent recurrence chains per warp give the ILP needed to hide the
// per-step serial chain (LDS -> dot -> activations -> STS -> syncwarp).
//
// Lane j owns hidden unit j (gate rows j, j+32, j+64, j+96).
// k-pair packed dots with fma.rn.f32x2 against h broadcast from smem
// (8 LDS.128 per batch-step).
//
// Activation prescales folded into weights/biases:
//   sigmoid(a) = rcp(1 + ex2(P_SIG*a)),        P_SIG  = -log2(e)
//   tanh(a)    = 1 - 2*rcp(1 + ex2(P_TANH*a)), P_TANH = 2*log2(e)

#define NB 4  // batches per warp

__global__ void __launch_bounds__(128, 2) lstm_h32_kernel(
    const float* __restrict__ x,      // [B, 512]
    const float* __restrict__ W_ih,   // [128]
    const float* __restrict__ W_hh,   // [128, 32]
    const float* __restrict__ b_ih,   // [128]
    const float* __restrict__ b_hh,   // [128]
    const float* __restrict__ W_lin,  // [32]
    const float* __restrict__ b_lin,  // [1]
    float* __restrict__ out)          // [B]
{
    __shared__ float swhh[128 * 34];                 // prologue staging
    __shared__ __align__(16) float hbuf[4][NB][2][32]; // [warp][batch][parity][k]

    const int tid = threadIdx.x;
    for (int i = tid; i < 128 * 32; i += 128)
        swhh[(i >> 5) * 34 + (i & 31)] = W_hh[i];
    __syncthreads();

    const int w = tid >> 5;
    const int j = tid & 31;
    const int b0 = (blockIdx.x * 4 + w) * NB;

    const float P_SIG  = -1.4426950408889634f;
    const float P_TANH =  2.8853900817779268f;
    const float PS[4] = {P_SIG, P_SIG, P_TANH, P_SIG};

    // Per-lane recurrent weights, prescaled, k-pair packed (128 regs).
    float2 wv[4][16];
    #pragma unroll
    for (int g = 0; g < 4; ++g) {
        const float* row = &swhh[(j + 32 * g) * 34];
        #pragma unroll
        for (int q = 0; q < 16; ++q) {
            float2 t = *reinterpret_cast<const float2*>(row + 2 * q);
            wv[g][q] = make_float2(PS[g] * t.x, PS[g] * t.y);
        }
    }

    float pwih[4], pb[4];
    #pragma unroll
    for (int g = 0; g < 4; ++g) {
        pwih[g] = PS[g] * W_ih[j + 32 * g];
        pb[g]   = PS[g] * (b_ih[j + 32 * g] + b_hh[j + 32 * g]);
    }

    float c[NB], h[NB];
    #pragma unroll
    for (int bb = 0; bb < NB; ++bb) {
        c[bb] = 0.0f; h[bb] = 0.0f;
        hbuf[w][bb][0][j] = 0.0f;
    }
    __syncwarp();

    for (int t0 = 0; t0 < 512; t0 += 32) {
        // Coalesced prefetch: 32 timesteps per batch.
        float xv[NB];
        #pragma unroll
        for (int bb = 0; bb < NB; ++bb)
            xv[bb] = x[(size_t)(b0 + bb) * 512 + t0 + j];

        #pragma unroll 2
        for (int tt = 0; tt < 32; ++tt) {
            const int pr = tt & 1;

            #pragma unroll
            for (int bb = 0; bb < NB; ++bb) {
                const float xt = __shfl_sync(FULL_MASK, xv[bb], tt);

                float2 acc0[4], acc1[4];
                #pragma unroll
                for (int g = 0; g < 4; ++g) {
                    acc0[g] = make_float2(fmaf(xt, pwih[g], pb[g]), 0.0f);
                    acc1[g] = make_float2(0.0f, 0.0f);
                }
                const float4* hb =
                    reinterpret_cast<const float4*>(&hbuf[w][bb][pr][0]);
                #pragma unroll
                for (int q2 = 0; q2 < 8; ++q2) {
                    const float4 hv = hb[q2];          // broadcast LDS.128
                    const float2 hA = make_float2(hv.x, hv.y);
                    const float2 hB = make_float2(hv.z, hv.w);
                    #pragma unroll
                    for (int g = 0; g < 4; ++g) {
                        acc0[g] = ffma2(hA, wv[g][2 * q2    ], acc0[g]);
                        acc1[g] = ffma2(hB, wv[g][2 * q2 + 1], acc1[g]);
                    }
                }
                float a[4];
                #pragma unroll
                for (int g = 0; g < 4; ++g) {
                    const float2 m = fadd2(acc0[g], acc1[g]);
                    a[g] = m.x + m.y;
                }

                const float si = rcpa(1.0f + ex2a(a[0]));
                const float sf = rcpa(1.0f + ex2a(a[1]));
                const float tg = fmaf(-2.0f, rcpa(1.0f + ex2a(a[2])), 1.0f);
                const float so = rcpa(1.0f + ex2a(a[3]));

                c[bb] = fmaf(sf, c[bb], si * tg);
                const float tc =
                    fmaf(-2.0f, rcpa(1.0f + ex2a(c[bb] * P_TANH)), 1.0f);
                h[bb] = so * tc;
                hbuf[w][bb][pr ^ 1][j] = h[bb];        // STS.32
            }
            __syncwarp();
        }
    }

    // Epilogue: out[b] = dot(h, W_lin) + b_lin
    const float wl = W_lin[j];
    #pragma unroll
    for (int bb = 0; bb < NB; ++bb) {
        float v = h[bb] * wl;
        #pragma unroll
        for (int off = 16; off; off >>= 1)
            v += __shfl_xor_sync(FULL_MASK, v, off);
        if (j == 0) out[b0 + bb] = v + b_lin[0];
    }
}

extern "C" void kernel_launch(void* const* d_in, const int* in_sizes, int n_in,
                              void* d_out, int out_size) {
    const float* x     = (const float*)d_in[0];
    const float* W_ih  = (const float*)d_in[1];
    const float* W_hh  = (const float*)d_in[2];
    const float* b_ih  = (const float*)d_in[3];
    const float* b_hh  = (const float*)d_in[4];
    const float* W_lin = (const float*)d_in[5];
    const float* b_lin = (const float*)d_in[6];
    float* out = (float*)d_out;

    // 8192 batches / (4 warps * 4 batches per warp) = 512 CTAs.
    lstm_h32_kernel<<<512, 128>>>(x, W_ih, W_hh, b_ih, b_hh, W_lin, b_lin, out);
}

// round 5
// speedup vs baseline: 1.6115x; 1.6115x over previous
#include <cuda_runtime.h>

#define FULL_MASK 0xffffffffu

// ---------- packed f32x2 + fast-math helpers ----------
__device__ __forceinline__ float2 ffma2(float2 a, float2 b, float2 c) {
    unsigned long long au = *reinterpret_cast<unsigned long long*>(&a);
    unsigned long long bu = *reinterpret_cast<unsigned long long*>(&b);
    unsigned long long cu = *reinterpret_cast<unsigned long long*>(&c);
    unsigned long long du;
    asm("fma.rn.f32x2 %0, %1, %2, %3;" : "=l"(du) : "l"(au), "l"(bu), "l"(cu));
    return *reinterpret_cast<float2*>(&du);
}
__device__ __forceinline__ float tanha(float x) {
    float r; asm("tanh.approx.f32 %0, %1;" : "=f"(r) : "f"(x)); return r;
}

// H=32, 4H=128, I=1, T=512, B=8192.
//
// R2 shape: one warp = two batch elements, lane j owns hidden unit j
// (gate rows j, j+32, j+64, j+96), k-pair packed fma.rn.f32x2 dots against
// h broadcast from a per-warp double-buffered smem ring.
//
// R5 deltas:
//  * activations via MUFU.TANH (tanh.approx):
//      sigmoid(u) = 0.5 + 0.5*tanh(0.5*u)  -> 0.5 folded into prescale
//      tanh(u)    = tanh(u)                -> prescale 1
//    5 MUFU per batch-step instead of 10; much shorter dep chain.
//  * 3 CTAs/SM (launch_bounds(128,3)); single acc chain per gate to fit regs.

__global__ void __launch_bounds__(128, 3) lstm_h32_kernel(
    const float* __restrict__ x,      // [B, 512]
    const float* __restrict__ W_ih,   // [128]
    const float* __restrict__ W_hh,   // [128, 32]
    const float* __restrict__ b_ih,   // [128]
    const float* __restrict__ b_hh,   // [128]
    const float* __restrict__ W_lin,  // [32]
    const float* __restrict__ b_lin,  // [1]
    float* __restrict__ out)          // [B]
{
    __shared__ float swhh[128 * 34];                   // prologue staging
    __shared__ __align__(16) float hbuf[4][2][2][32];  // [warp][batch][parity][k]

    const int tid = threadIdx.x;
    for (int i = tid; i < 128 * 32; i += 128)
        swhh[(i >> 5) * 34 + (i & 31)] = W_hh[i];
    __syncthreads();

    const int w = tid >> 5;
    const int j = tid & 31;
    const int b0 = (blockIdx.x * 4 + w) * 2;

    // Prescales: sigmoid rows (i,f,o) get 0.5 (sigmoid-via-tanh),
    // tanh row (g) gets 1.
    const float PS[4] = {0.5f, 0.5f, 1.0f, 0.5f};

    // Per-lane recurrent weights, prescaled, k-pair packed (128 regs).
    float2 wv[4][16];
    #pragma unroll
    for (int g = 0; g < 4; ++g) {
        const float* row = &swhh[(j + 32 * g) * 34];
        #pragma unroll
        for (int q = 0; q < 16; ++q) {
            float2 t = *reinterpret_cast<const float2*>(row + 2 * q);
            wv[g][q] = make_float2(PS[g] * t.x, PS[g] * t.y);
        }
    }

    float pwih[4], pb[4];
    #pragma unroll
    for (int g = 0; g < 4; ++g) {
        pwih[g] = PS[g] * W_ih[j + 32 * g];
        pb[g]   = PS[g] * (b_ih[j + 32 * g] + b_hh[j + 32 * g]);
    }

    float c[2] = {0.0f, 0.0f};
    float h[2] = {0.0f, 0.0f};
    hbuf[w][0][0][j] = 0.0f;
    hbuf[w][1][0][j] = 0.0f;
    __syncwarp();

    for (int t0 = 0; t0 < 512; t0 += 32) {
        // Coalesced prefetch of 32 timesteps for both batches.
        const float xv0 = x[(size_t)(b0    ) * 512 + t0 + j];
        const float xv1 = x[(size_t)(b0 + 1) * 512 + t0 + j];

        #pragma unroll 2
        for (int tt = 0; tt < 32; ++tt) {
            const int pr = tt & 1;
            const float xt[2] = {__shfl_sync(FULL_MASK, xv0, tt),
                                 __shfl_sync(FULL_MASK, xv1, tt)};

            #pragma unroll
            for (int bb = 0; bb < 2; ++bb) {
                // Single accumulator chain per gate (8 regs total).
                float2 acc[4];
                #pragma unroll
                for (int g = 0; g < 4; ++g)
                    acc[g] = make_float2(fmaf(xt[bb], pwih[g], pb[g]), 0.0f);

                const float4* hb =
                    reinterpret_cast<const float4*>(&hbuf[w][bb][pr][0]);
                #pragma unroll
                for (int q2 = 0; q2 < 8; ++q2) {
                    const float4 hv = hb[q2];          // broadcast LDS.128
                    const float2 hA = make_float2(hv.x, hv.y);
                    const float2 hB = make_float2(hv.z, hv.w);
                    #pragma unroll
                    for (int g = 0; g < 4; ++g) {
                        acc[g] = ffma2(hA, wv[g][2 * q2    ], acc[g]);
                        acc[g] = ffma2(hB, wv[g][2 * q2 + 1], acc[g]);
                    }
                }
                float a[4];
                #pragma unroll
                for (int g = 0; g < 4; ++g)
                    a[g] = acc[g].x + acc[g].y;

                // tanh-based activations (prescale already applied):
                //   a[0..3] = 0.5*u_i, 0.5*u_f, u_g, 0.5*u_o
                const float si = fmaf(0.5f, tanha(a[0]), 0.5f);
                const float sf = fmaf(0.5f, tanha(a[1]), 0.5f);
                const float tg = tanha(a[2]);
                const float so = fmaf(0.5f, tanha(a[3]), 0.5f);

                c[bb] = fmaf(sf, c[bb], si * tg);
                const float tc = tanha(c[bb]);
                h[bb] = so * tc;
                hbuf[w][bb][pr ^ 1][j] = h[bb];        // STS.32
            }
            __syncwarp();
        }
    }

    // Epilogue: out[b] = dot(h, W_lin) + b_lin
    const float wl = W_lin[j];
    #pragma unroll
    for (int bb = 0; bb < 2; ++bb) {
        float v = h[bb] * wl;
        #pragma unroll
        for (int off = 16; off; off >>= 1)
            v += __shfl_xor_sync(FULL_MASK, v, off);
        if (j == 0) out[b0 + bb] = v + b_lin[0];
    }
}

extern "C" void kernel_launch(void* const* d_in, const int* in_sizes, int n_in,
                              void* d_out, int out_size) {
    const float* x     = (const float*)d_in[0];
    const float* W_ih  = (const float*)d_in[1];
    const float* W_hh  = (const float*)d_in[2];
    const float* b_ih  = (const float*)d_in[3];
    const float* b_hh  = (const float*)d_in[4];
    const float* W_lin = (const float*)d_in[5];
    const float* b_lin = (const float*)d_in[6];
    float* out = (float*)d_out;

    // 8192 batches / (4 warps * 2 batches per warp) = 1024 CTAs.
    lstm_h32_kernel<<<1024, 128>>>(x, W_ih, W_hh, b_ih, b_hh, W_lin, b_lin, out);
}

// round 6
// speedup vs baseline: 1.7036x; 1.0572x over previous
#include <cuda_runtime.h>

#define FULL_MASK 0xffffffffu

// ---------- packed f32x2 + fast-math helpers ----------
__device__ __forceinline__ float2 ffma2(float2 a, float2 b, float2 c) {
    unsigned long long au = *reinterpret_cast<unsigned long long*>(&a);
    unsigned long long bu = *reinterpret_cast<unsigned long long*>(&b);
    unsigned long long cu = *reinterpret_cast<unsigned long long*>(&c);
    unsigned long long du;
    asm("fma.rn.f32x2 %0, %1, %2, %3;" : "=l"(du) : "l"(au), "l"(bu), "l"(cu));
    return *reinterpret_cast<float2*>(&du);
}
__device__ __forceinline__ float tanha(float x) {
    float r; asm("tanh.approx.f32 %0, %1;" : "=f"(r) : "f"(x)); return r;
}

// H=32, 4H=128, I=1, T=512, B=8192.
//
// R2 shape: one warp = two batch elements, lane j owns hidden unit j
// (gate rows j, j+32, j+64, j+96), k-pair packed fma.rn.f32x2 dots against
// h broadcast from a per-warp double-buffered smem ring.
//
// R5 deltas:
//  * activations via MUFU.TANH (tanh.approx):
//      sigmoid(u) = 0.5 + 0.5*tanh(0.5*u)  -> 0.5 folded into prescale
//      tanh(u)    = tanh(u)                -> prescale 1
//    5 MUFU per batch-step instead of 10; much shorter dep chain.
//  * 3 CTAs/SM (launch_bounds(128,3)); single acc chain per gate to fit regs.

__global__ void __launch_bounds__(128, 3) lstm_h32_kernel(
    const float* __restrict__ x,      // [B, 512]
    const float* __restrict__ W_ih,   // [128]
    const float* __restrict__ W_hh,   // [128, 32]
    const float* __restrict__ b_ih,   // [128]
    const float* __restrict__ b_hh,   // [128]
    const float* __restrict__ W_lin,  // [32]
    const float* __restrict__ b_lin,  // [1]
    float* __restrict__ out)          // [B]
{
    __shared__ float swhh[128 * 34];                   // prologue staging
    __shared__ __align__(16) float hbuf[4][2][2][32];  // [warp][batch][parity][k]

    const int tid = threadIdx.x;
    for (int i = tid; i < 128 * 32; i += 128)
        swhh[(i >> 5) * 34 + (i & 31)] = W_hh[i];
    __syncthreads();

    const int w = tid >> 5;
    const int j = tid & 31;
    const int b0 = (blockIdx.x * 4 + w) * 2;

    // Prescales: sigmoid rows (i,f,o) get 0.5 (sigmoid-via-tanh),
    // tanh row (g) gets 1.
    const float PS[4] = {0.5f, 0.5f, 1.0f, 0.5f};

    // Per-lane recurrent weights, prescaled, k-pair packed (128 regs).
    float2 wv[4][16];
    #pragma unroll
    for (int g = 0; g < 4; ++g) {
        const float* row = &swhh[(j + 32 * g) * 34];
        #pragma unroll
        for (int q = 0; q < 16; ++q) {
            float2 t = *reinterpret_cast<const float2*>(row + 2 * q);
            wv[g][q] = make_float2(PS[g] * t.x, PS[g] * t.y);
        }
    }

    float pwih[4], pb[4];
    #pragma unroll
    for (int g = 0; g < 4; ++g) {
        pwih[g] = PS[g] * W_ih[j + 32 * g];
        pb[g]   = PS[g] * (b_ih[j + 32 * g] + b_hh[j + 32 * g]);
    }

    float c[2] = {0.0f, 0.0f};
    float h[2] = {0.0f, 0.0f};
    hbuf[w][0][0][j] = 0.0f;
    hbuf[w][1][0][j] = 0.0f;
    __syncwarp();

    for (int t0 = 0; t0 < 512; t0 += 32) {
        // Coalesced prefetch of 32 timesteps for both batches.
        const float xv0 = x[(size_t)(b0    ) * 512 + t0 + j];
        const float xv1 = x[(size_t)(b0 + 1) * 512 + t0 + j];

        #pragma unroll 2
        for (int tt = 0; tt < 32; ++tt) {
            const int pr = tt & 1;
            const float xt[2] = {__shfl_sync(FULL_MASK, xv0, tt),
                                 __shfl_sync(FULL_MASK, xv1, tt)};

            #pragma unroll
            for (int bb = 0; bb < 2; ++bb) {
                // Single accumulator chain per gate (8 regs total).
                float2 acc[4];
                #pragma unroll
                for (int g = 0; g < 4; ++g)
                    acc[g] = make_float2(fmaf(xt[bb], pwih[g], pb[g]), 0.0f);

                const float4* hb =
                    reinterpret_cast<const float4*>(&hbuf[w][bb][pr][0]);
                #pragma unroll
                for (int q2 = 0; q2 < 8; ++q2) {
                    const float4 hv = hb[q2];          // broadcast LDS.128
                    const float2 hA = make_float2(hv.x, hv.y);
                    const float2 hB = make_float2(hv.z, hv.w);
                    #pragma unroll
                    for (int g = 0; g < 4; ++g) {
                        acc[g] = ffma2(hA, wv[g][2 * q2    ], acc[g]);
                        acc[g] = ffma2(hB, wv[g][2 * q2 + 1], acc[g]);
                    }
                }
                float a[4];
                #pragma unroll
                for (int g = 0; g < 4; ++g)
                    a[g] = acc[g].x + acc[g].y;

                // tanh-based activations (prescale already applied):
                //   a[0..3] = 0.5*u_i, 0.5*u_f, u_g, 0.5*u_o
                const float si = fmaf(0.5f, tanha(a[0]), 0.5f);
                const float sf = fmaf(0.5f, tanha(a[1]), 0.5f);
                const float tg = tanha(a[2]);
                const float so = fmaf(0.5f, tanha(a[3]), 0.5f);

                c[bb] = fmaf(sf, c[bb], si * tg);
                const float tc = tanha(c[bb]);
                h[bb] = so * tc;
                hbuf[w][bb][pr ^ 1][j] = h[bb];        // STS.32
            }
            __syncwarp();
        }
    }

    // Epilogue: out[b] = dot(h, W_lin) + b_lin
    const float wl = W_lin[j];
    #pragma unroll
    for (int bb = 0; bb < 2; ++bb) {
        float v = h[bb] * wl;
        #pragma unroll
        for (int off = 16; off; off >>= 1)
            v += __shfl_xor_sync(FULL_MASK, v, off);
        if (j == 0) out[b0 + bb] = v + b_lin[0];
    }
}

extern "C" void kernel_launch(void* const* d_in, const int* in_sizes, int n_in,
                              void* d_out, int out_size) {
    const float* x     = (const float*)d_in[0];
    const float* W_ih  = (const float*)d_in[1];
    const float* W_hh  = (const float*)d_in[2];
    const float* b_ih  = (const float*)d_in[3];
    const float* b_hh  = (const float*)d_in[4];
    const float* W_lin = (const float*)d_in[5];
    const float* b_lin = (const float*)d_in[6];
    float* out = (float*)d_out;

    // 8192 batches / (4 warps * 2 batches per warp) = 1024 CTAs.
    lstm_h32_kernel<<<1024, 128>>>(x, W_ih, W_hh, b_ih, b_hh, W_lin, b_lin, out);
}

// round 7
// speedup vs baseline: 1.8619x; 1.0929x over previous
#include <cuda_runtime.h>
#include <cstdint>

#define FULL_MASK 0xffffffffu

__device__ __forceinline__ float tanha(float x) {
    float r; asm("tanh.approx.f32 %0, %1;" : "=f"(r) : "f"(x)); return r;
}
// pack two f32 -> bf16x2 (hi in upper 16, lo in lower 16)
__device__ __forceinline__ uint32_t pack_bf16(float hi, float lo) {
    uint32_t r; asm("cvt.rn.bf16x2.f32 %0, %1, %2;" : "=r"(r) : "f"(hi), "f"(lo));
    return r;
}
__device__ __forceinline__ float bf_lo(uint32_t u) { return __uint_as_float(u << 16); }
__device__ __forceinline__ float bf_hi(uint32_t u) { return __uint_as_float(u & 0xffff0000u); }

// D[16,8] += A[16,16] * B[16,8], bf16 in, f32 accum. Row-major A, col-major B.
__device__ __forceinline__ void mma16816(float4& d,
                                         uint32_t a0, uint32_t a1,
                                         uint32_t a2, uint32_t a3,
                                         uint32_t b0, uint32_t b1) {
    asm("mma.sync.aligned.m16n8k16.row.col.f32.bf16.bf16.f32 "
        "{%0,%1,%2,%3}, {%4,%5,%6,%7}, {%8,%9}, {%0,%1,%2,%3};"
        : "+f"(d.x), "+f"(d.y), "+f"(d.z), "+f"(d.w)
        : "r"(a0), "r"(a1), "r"(a2), "r"(a3), "r"(b0), "r"(b1));
}

// H=32, 4H=128 gates (g-major: n = 32*g + u), I=1, T=512, B=8192.
//
// Warp = 8 batches (M16 rows 0-7 real, 8-15 zero-padded).
// Lane l: gr = l/4 (batch row), gc = l%4.
// D frag tile j (n = 8j..8j+7): lane holds D[gr][8j+2gc], D[gr][8j+2gc+1]
//   -> gate g=j/4, units u = 8*(j%4)+2gc, +1 of batch gr.
// A frag k-slot (k = 2gc + 8*slot + 16*kfrag) == unit index -> the h values a
// lane computes are EXACTLY its own A-operand slots next step. Register-
// resident recurrence: no smem/shuffle/syncwarp in the steady-state loop.
//
// Weights: Wp = PS[g]*W_hh  (PS = 0.5 for sigmoid gates i,f,o; 1.0 for g),
// split Wp ~= Bh + Bl (bf16 each); h ~= hh + hl (bf16 each).
// D = Ah*Bh + Al*Bh + Ah*Bl, C-init = PS*(x*W_ih + b_ih + b_hh) in fp32.
// Activations: sigmoid(u)=0.5+0.5*tanh(0.5u) (PS folded), tanh via MUFU.

__global__ void __launch_bounds__(256, 1) lstm_mma_kernel(
    const float* __restrict__ x,      // [B, 512]
    const float* __restrict__ W_ih,   // [128]
    const float* __restrict__ W_hh,   // [128, 32]
    const float* __restrict__ b_ih,   // [128]
    const float* __restrict__ b_hh,   // [128]
    const float* __restrict__ W_lin,  // [32]
    const float* __restrict__ b_lin,  // [1]
    float* __restrict__ out)          // [B]
{
    // wb4[m] = (PS*W_ih[2m], PS*(b_ih+b_hh)[2m], PS*W_ih[2m+1], PS*bias[2m+1])
    __shared__ __align__(16) float4 wb4[64];
    __shared__ __align__(16) float xs[8][8][36];  // [warp][batch][step] (padded)

    const int tid = threadIdx.x;
    const int w   = tid >> 5;
    const int l   = tid & 31;
    const int gr  = l >> 2;   // batch row within warp
    const int gc  = l & 3;

    if (tid < 64) {
        const int n0 = 2 * tid, n1 = n0 + 1;
        const float ps0 = ((n0 >> 5) == 2) ? 1.0f : 0.5f;
        const float ps1 = ((n1 >> 5) == 2) ? 1.0f : 0.5f;
        wb4[tid] = make_float4(ps0 * W_ih[n0], ps0 * (b_ih[n0] + b_hh[n0]),
                               ps1 * W_ih[n1], ps1 * (b_ih[n1] + b_hh[n1]));
    }
    __syncthreads();

    // ---- B fragments (persistent registers): BH/BL[2*j + kfrag] ----
    uint2 BH[32], BL[32];
    #pragma unroll
    for (int j = 0; j < 16; ++j) {
        const int n = 8 * j + gr;
        const float ps = ((n >> 5) == 2) ? 1.0f : 0.5f;
        const float* wr = W_hh + n * 32;
        #pragma unroll
        for (int kk = 0; kk < 2; ++kk) {
            const int k0 = kk * 16 + 2 * gc;
            const float w00 = ps * wr[k0],     w01 = ps * wr[k0 + 1];
            const float w10 = ps * wr[k0 + 8], w11 = ps * wr[k0 + 9];
            const uint32_t b0h = pack_bf16(w01, w00);
            const uint32_t b1h = pack_bf16(w11, w10);
            const uint32_t b0l = pack_bf16(w01 - bf_hi(b0h), w00 - bf_lo(b0h));
            const uint32_t b1l = pack_bf16(w11 - bf_hi(b1h), w10 - bf_lo(b1h));
            BH[2 * j + kk] = make_uint2(b0h, b1h);
            BL[2 * j + kk] = make_uint2(b0l, b1l);
        }
    }

    const int base = (blockIdx.x * 8 + w) * 8;  // warp's first batch
    const float* xb = x + (size_t)(base + gr) * 512;

    // A fragments: ahi/alo[kfrag][slot]; pad rows (a1,a3) stay zero.
    uint32_t ahi[2][2] = {{0u, 0u}, {0u, 0u}};
    uint32_t alo[2][2] = {{0u, 0u}, {0u, 0u}};
    const uint32_t ZR = 0u;

    float c[8], h[8];
    #pragma unroll
    for (int i = 0; i < 8; ++i) { c[i] = 0.0f; h[i] = 0.0f; }

    for (int t0 = 0; t0 < 512; t0 += 32) {
        // chunk load: lane (gr,gc) holds steps t0+8gc .. +7 of batch gr
        const float* p = xb + t0 + 8 * gc;
        const float4 v0 = *reinterpret_cast<const float4*>(p);
        const float4 v1 = *reinterpret_cast<const float4*>(p + 4);
        __syncwarp();   // prior-chunk reads done
        *reinterpret_cast<float4*>(&xs[w][gr][8 * gc])     = v0;
        *reinterpret_cast<float4*>(&xs[w][gr][8 * gc + 4]) = v1;
        __syncwarp();   // stores visible

        #pragma unroll 1
        for (int tc = 0; tc < 32; ++tc) {
            const float xt = xs[w][gr][tc];

            uint32_t nahi[2][2], nalo[2][2];

            #pragma unroll
            for (int jj = 0; jj < 4; ++jj) {
                float4 d[4];
                #pragma unroll
                for (int g = 0; g < 4; ++g) {
                    const int j = 4 * g + jj;
                    const float4 q = wb4[16 * g + 4 * jj + gc];
                    d[g].x = fmaf(xt, q.x, q.y);   // fp32 x*W_ih + bias (PS'd)
                    d[g].y = fmaf(xt, q.z, q.w);
                    d[g].z = 0.0f; d[g].w = 0.0f;
                    mma16816(d[g], ahi[0][0], ZR, ahi[0][1], ZR,
                             BH[2 * j].x, BH[2 * j].y);
                    mma16816(d[g], ahi[1][0], ZR, ahi[1][1], ZR,
                             BH[2 * j + 1].x, BH[2 * j + 1].y);
                    mma16816(d[g], alo[0][0], ZR, alo[0][1], ZR,
                             BH[2 * j].x, BH[2 * j].y);
                    mma16816(d[g], alo[1][0], ZR, alo[1][1], ZR,
                             BH[2 * j + 1].x, BH[2 * j + 1].y);
                    mma16816(d[g], ahi[0][0], ZR, ahi[0][1], ZR,
                             BL[2 * j].x, BL[2 * j].y);
                    mma16816(d[g], ahi[1][0], ZR, ahi[1][1], ZR,
                             BL[2 * j + 1].x, BL[2 * j + 1].y);
                }
                // activations: cells (batch gr, units 8jj+2gc, 8jj+2gc+1)
                #pragma unroll
                for (int e = 0; e < 2; ++e) {
                    const float pi = e ? d[0].y : d[0].x;
                    const float pf = e ? d[1].y : d[1].x;
                    const float pg = e ? d[2].y : d[2].x;
                    const float po = e ? d[3].y : d[3].x;
                    const float ti = tanha(pi);
                    const float tf = tanha(pf);
                    const float tg = tanha(pg);
                    const float to = tanha(po);
                    const float si = fmaf(0.5f, ti, 0.5f);
                    const float sf = fmaf(0.5f, tf, 0.5f);
                    const float so = fmaf(0.5f, to, 0.5f);
                    const int ci = 2 * jj + e;
                    c[ci] = fmaf(sf, c[ci], si * tg);
                    h[ci] = so * tanha(c[ci]);
                }
                // h -> bf16 hi/lo packed into next-step A slots
                const uint32_t ph = pack_bf16(h[2 * jj + 1], h[2 * jj]);
                const float f0 = bf_lo(ph), f1 = bf_hi(ph);
                const uint32_t pl = pack_bf16(h[2 * jj + 1] - f1,
                                              h[2 * jj] - f0);
                nahi[jj >> 1][jj & 1] = ph;
                nalo[jj >> 1][jj & 1] = pl;
            }

            ahi[0][0] = nahi[0][0]; ahi[0][1] = nahi[0][1];
            ahi[1][0] = nahi[1][0]; ahi[1][1] = nahi[1][1];
            alo[0][0] = nalo[0][0]; alo[0][1] = nalo[0][1];
            alo[1][0] = nalo[1][0]; alo[1][1] = nalo[1][1];
        }
    }

    // Epilogue: out[b] = dot(h, W_lin) + b_lin; lanes of a batch-quad hold
    // disjoint units -> quad reduction via shfl_xor 1,2.
    float v = 0.0f;
    #pragma unroll
    for (int jj = 0; jj < 4; ++jj) {
        v = fmaf(h[2 * jj],     W_lin[8 * jj + 2 * gc],     v);
        v = fmaf(h[2 * jj + 1], W_lin[8 * jj + 2 * gc + 1], v);
    }
    v += __shfl_xor_sync(FULL_MASK, v, 1);
    v += __shfl_xor_sync(FULL_MASK, v, 2);
    if (gc == 0) out[base + gr] = v + b_lin[0];
}

extern "C" void kernel_launch(void* const* d_in, const int* in_sizes, int n_in,
                              void* d_out, int out_size) {
    const float* x     = (const float*)d_in[0];
    const float* W_ih  = (const float*)d_in[1];
    const float* W_hh  = (const float*)d_in[2];
    const float* b_ih  = (const float*)d_in[3];
    const float* b_hh  = (const float*)d_in[4];
    const float* W_lin = (const float*)d_in[5];
    const float* b_lin = (const float*)d_in[6];
    float* out = (float*)d_out;

    // 8192 batches / (8 warps * 8 batches per warp) = 128 CTAs of 256 threads.
    lstm_mma_kernel<<<128, 256>>>(x, W_ih, W_hh, b_ih, b_hh, W_lin, b_lin, out);
}

// round 8
// speedup vs baseline: 2.8560x; 1.5339x over previous
#include <cuda_runtime.h>
#include <cstdint>

#define FULL_MASK 0xffffffffu

__device__ __forceinline__ float tanha(float x) {
    float r; asm("tanh.approx.f32 %0, %1;" : "=f"(r) : "f"(x)); return r;
}
// pack two f32 -> bf16x2 (hi arg in upper 16 bits, lo arg in lower 16)
__device__ __forceinline__ uint32_t pack_bf16(float hi, float lo) {
    uint32_t r; asm("cvt.rn.bf16x2.f32 %0, %1, %2;" : "=r"(r) : "f"(hi), "f"(lo));
    return r;
}
__device__ __forceinline__ float bf_lo(uint32_t u) { return __uint_as_float(u << 16); }
__device__ __forceinline__ float bf_hi(uint32_t u) { return __uint_as_float(u & 0xffff0000u); }

// D[16,8] += A[16,16] * B[16,8], bf16 in, f32 accum. Row-major A, col-major B.
__device__ __forceinline__ void mma16816(float4& d,
                                         uint32_t a0, uint32_t a1,
                                         uint32_t a2, uint32_t a3,
                                         uint32_t b0, uint32_t b1) {
    asm("mma.sync.aligned.m16n8k16.row.col.f32.bf16.bf16.f32 "
        "{%0,%1,%2,%3}, {%4,%5,%6,%7}, {%8,%9}, {%0,%1,%2,%3};"
        : "+f"(d.x), "+f"(d.y), "+f"(d.z), "+f"(d.w)
        : "r"(a0), "r"(a1), "r"(a2), "r"(a3), "r"(b0), "r"(b1));
}

// H=32, 4H=128 gates (g-major: n = 32*g + u), I=1, T=512, B=8192.
//
// Warp = SIXTEEN batches: M16 rows 0-7 = batches base..base+7 (D frag .x/.y,
// A slots a0/a2), rows 8-15 = batches base+8..base+15 (D frag .z/.w, A slots
// a1/a3). Lane l: gr = l/4, gc = l%4; owns batches base+gr and base+gr+8,
// units 8jj+2gc, 8jj+2gc+1 for jj=0..3 of each.
// The h values a lane computes are exactly its own A-operand slots next step:
// register-resident recurrence, no smem h exchange.
//
// Weights Wp = PS[g]*W_hh (PS=0.5 sigmoid gates i,f,o; 1.0 for g), split
// Wp ~= BH + BL (bf16 each); h ~= h_hi + h_lo (bf16 each).
// D = Ah*BH + Al*BH + Ah*BL; C-init = PS*(x*W_ih + bias) in fp32.
// BH lives in registers (64), BL in smem (reloaded, conflict-free LDS.64).
// Activations: sigmoid(u)=0.5+0.5*tanh(0.5u) (PS folded), tanh via MUFU.

__global__ void __launch_bounds__(128, 1) lstm_mma_kernel(
    const float* __restrict__ x,      // [B, 512]
    const float* __restrict__ W_ih,   // [128]
    const float* __restrict__ W_hh,   // [128, 32]
    const float* __restrict__ b_ih,   // [128]
    const float* __restrict__ b_hh,   // [128]
    const float* __restrict__ W_lin,  // [32]
    const float* __restrict__ b_lin,  // [1]
    float* __restrict__ out)          // [B]
{
    // wb4[m] = (PS*W_ih[2m], PS*(b_ih+b_hh)[2m], PS*W_ih[2m+1], PS*bias[2m+1])
    __shared__ __align__(16) float4 wb4[64];
    __shared__ __align__(16) uint2 sBL[32][32];   // [2*j+kk][lane]
    __shared__ __align__(16) float xs[4][16][36]; // [warp][batch][step] padded

    const int tid = threadIdx.x;
    const int w   = tid >> 5;
    const int l   = tid & 31;
    const int gr  = l >> 2;
    const int gc  = l & 3;

    if (tid < 64) {
        const int n0 = 2 * tid, n1 = n0 + 1;
        const float ps0 = ((n0 >> 5) == 2) ? 1.0f : 0.5f;
        const float ps1 = ((n1 >> 5) == 2) ? 1.0f : 0.5f;
        wb4[tid] = make_float4(ps0 * W_ih[n0], ps0 * (b_ih[n0] + b_hh[n0]),
                               ps1 * W_ih[n1], ps1 * (b_ih[n1] + b_hh[n1]));
    }

    // ---- B fragments: BH in registers, BL in smem ----
    uint2 BH[32];
    #pragma unroll
    for (int j = 0; j < 16; ++j) {
        const int n = 8 * j + gr;
        const float ps = ((n >> 5) == 2) ? 1.0f : 0.5f;
        const float* wr = W_hh + n * 32;
        #pragma unroll
        for (int kk = 0; kk < 2; ++kk) {
            const int k0 = kk * 16 + 2 * gc;
            const float w00 = ps * wr[k0],     w01 = ps * wr[k0 + 1];
            const float w10 = ps * wr[k0 + 8], w11 = ps * wr[k0 + 9];
            const uint32_t b0h = pack_bf16(w01, w00);
            const uint32_t b1h = pack_bf16(w11, w10);
            BH[2 * j + kk] = make_uint2(b0h, b1h);
            if (w == 0) {
                const uint32_t b0l = pack_bf16(w01 - bf_hi(b0h), w00 - bf_lo(b0h));
                const uint32_t b1l = pack_bf16(w11 - bf_hi(b1h), w10 - bf_lo(b1h));
                sBL[2 * j + kk][l] = make_uint2(b0l, b1l);
            }
        }
    }
    __syncthreads();

    const int base = (blockIdx.x * 4 + w) * 16;  // warp's first batch
    // x staging: lane l loads batch (l>>1), steps [16*(l&1) .. +15] per chunk
    const float* xb = x + (size_t)(base + (l >> 1)) * 512 + 16 * (l & 1);
    float* xw = &xs[w][l >> 1][16 * (l & 1)];

    // A fragments [kfrag][slot]: hi/lo of batch group A (rows 0-7, a0/a2)
    // and batch group B (rows 8-15, a1/a3).
    uint32_t Ahi[2][2] = {{0u,0u},{0u,0u}}, Alo[2][2] = {{0u,0u},{0u,0u}};
    uint32_t Bhi[2][2] = {{0u,0u},{0u,0u}}, Blo[2][2] = {{0u,0u},{0u,0u}};

    float cA[8], hA[8], cB[8], hB[8];
    #pragma unroll
    for (int i = 0; i < 8; ++i) { cA[i]=0.f; hA[i]=0.f; cB[i]=0.f; hB[i]=0.f; }

    for (int t0 = 0; t0 < 512; t0 += 32) {
        const float4 v0 = *reinterpret_cast<const float4*>(xb + t0);
        const float4 v1 = *reinterpret_cast<const float4*>(xb + t0 + 4);
        const float4 v2 = *reinterpret_cast<const float4*>(xb + t0 + 8);
        const float4 v3 = *reinterpret_cast<const float4*>(xb + t0 + 12);
        __syncwarp();   // prior-chunk xs reads done
        *reinterpret_cast<float4*>(xw)      = v0;
        *reinterpret_cast<float4*>(xw + 4)  = v1;
        *reinterpret_cast<float4*>(xw + 8)  = v2;
        *reinterpret_cast<float4*>(xw + 12) = v3;
        __syncwarp();   // stores visible

        #pragma unroll 1
        for (int tc = 0; tc < 32; ++tc) {
            const float xtA = xs[w][gr][tc];
            const float xtB = xs[w][gr + 8][tc];

            uint32_t nAhi[2][2], nAlo[2][2], nBhi[2][2], nBlo[2][2];

            #pragma unroll
            for (int jj = 0; jj < 4; ++jj) {
                float4 d[4];
                #pragma unroll
                for (int g = 0; g < 4; ++g) {
                    const int j = 4 * g + jj;
                    const float4 q = wb4[16 * g + 4 * jj + gc];
                    d[g].x = fmaf(xtA, q.x, q.y);
                    d[g].y = fmaf(xtA, q.z, q.w);
                    d[g].z = fmaf(xtB, q.x, q.y);
                    d[g].w = fmaf(xtB, q.z, q.w);
                    const uint2 bl0 = sBL[2 * j][l];
                    const uint2 bl1 = sBL[2 * j + 1][l];
                    // Ah * BH (both kfrags)
                    mma16816(d[g], Ahi[0][0], Bhi[0][0], Ahi[0][1], Bhi[0][1],
                             BH[2 * j].x, BH[2 * j].y);
                    mma16816(d[g], Ahi[1][0], Bhi[1][0], Ahi[1][1], Bhi[1][1],
                             BH[2 * j + 1].x, BH[2 * j + 1].y);
                    // Al * BH
                    mma16816(d[g], Alo[0][0], Blo[0][0], Alo[0][1], Blo[0][1],
                             BH[2 * j].x, BH[2 * j].y);
                    mma16816(d[g], Alo[1][0], Blo[1][0], Alo[1][1], Blo[1][1],
                             BH[2 * j + 1].x, BH[2 * j + 1].y);
                    // Ah * BL
                    mma16816(d[g], Ahi[0][0], Bhi[0][0], Ahi[0][1], Bhi[0][1],
                             bl0.x, bl0.y);
                    mma16816(d[g], Ahi[1][0], Bhi[1][0], Ahi[1][1], Bhi[1][1],
                             bl1.x, bl1.y);
                }
                // ---- activations: batch A (d.x,d.y), batch B (d.z,d.w) ----
                #pragma unroll
                for (int e = 0; e < 2; ++e) {
                    const int ci = 2 * jj + e;
                    {   // batch A
                        const float pi = e ? d[0].y : d[0].x;
                        const float pf = e ? d[1].y : d[1].x;
                        const float pg = e ? d[2].y : d[2].x;
                        const float po = e ? d[3].y : d[3].x;
                        const float si = fmaf(0.5f, tanha(pi), 0.5f);
                        const float sf = fmaf(0.5f, tanha(pf), 0.5f);
                        const float tg = tanha(pg);
                        const float so = fmaf(0.5f, tanha(po), 0.5f);
                        cA[ci] = fmaf(sf, cA[ci], si * tg);
                        hA[ci] = so * tanha(cA[ci]);
                    }
                    {   // batch B
                        const float pi = e ? d[0].w : d[0].z;
                        const float pf = e ? d[1].w : d[1].z;
                        const float pg = e ? d[2].w : d[2].z;
                        const float po = e ? d[3].w : d[3].z;
                        const float si = fmaf(0.5f, tanha(pi), 0.5f);
                        const float sf = fmaf(0.5f, tanha(pf), 0.5f);
                        const float tg = tanha(pg);
                        const float so = fmaf(0.5f, tanha(po), 0.5f);
                        cB[ci] = fmaf(sf, cB[ci], si * tg);
                        hB[ci] = so * tanha(cB[ci]);
                    }
                }
                // pack h -> next-step A fragments (kfrag = jj>>1, slot = jj&1)
                {
                    const uint32_t pa = pack_bf16(hA[2*jj+1], hA[2*jj]);
                    const uint32_t la = pack_bf16(hA[2*jj+1] - bf_hi(pa),
                                                  hA[2*jj]   - bf_lo(pa));
                    const uint32_t pb = pack_bf16(hB[2*jj+1], hB[2*jj]);
                    const uint32_t lb = pack_bf16(hB[2*jj+1] - bf_hi(pb),
                                                  hB[2*jj]   - bf_lo(pb));
                    nAhi[jj >> 1][jj & 1] = pa;
                    nAlo[jj >> 1][jj & 1] = la;
                    nBhi[jj >> 1][jj & 1] = pb;
                    nBlo[jj >> 1][jj & 1] = lb;
                }
            }

            #pragma unroll
            for (int kf = 0; kf < 2; ++kf)
                #pragma unroll
                for (int s = 0; s < 2; ++s) {
                    Ahi[kf][s] = nAhi[kf][s]; Alo[kf][s] = nAlo[kf][s];
                    Bhi[kf][s] = nBhi[kf][s]; Blo[kf][s] = nBlo[kf][s];
                }
        }
    }

    // Epilogue: out[b] = dot(h, W_lin) + b_lin; quad reduction over gc.
    float vA = 0.0f, vB = 0.0f;
    #pragma unroll
    for (int jj = 0; jj < 4; ++jj) {
        const float wl0 = W_lin[8 * jj + 2 * gc];
        const float wl1 = W_lin[8 * jj + 2 * gc + 1];
        vA = fmaf(hA[2 * jj], wl0, vA); vA = fmaf(hA[2 * jj + 1], wl1, vA);
        vB = fmaf(hB[2 * jj], wl0, vB); vB = fmaf(hB[2 * jj + 1], wl1, vB);
    }
    vA += __shfl_xor_sync(FULL_MASK, vA, 1);
    vA += __shfl_xor_sync(FULL_MASK, vA, 2);
    vB += __shfl_xor_sync(FULL_MASK, vB, 1);
    vB += __shfl_xor_sync(FULL_MASK, vB, 2);
    if (gc == 0) {
        out[base + gr]     = vA + b_lin[0];
        out[base + gr + 8] = vB + b_lin[0];
    }
}

extern "C" void kernel_launch(void* const* d_in, const int* in_sizes, int n_in,
                              void* d_out, int out_size) {
    const float* x     = (const float*)d_in[0];
    const float* W_ih  = (const float*)d_in[1];
    const float* W_hh  = (const float*)d_in[2];
    const float* b_ih  = (const float*)d_in[3];
    const float* b_hh  = (const float*)d_in[4];
    const float* W_lin = (const float*)d_in[5];
    const float* b_lin = (const float*)d_in[6];
    float* out = (float*)d_out;

    // 8192 batches / (4 warps * 16 batches per warp) = 128 CTAs of 128 threads.
    lstm_mma_kernel<<<128, 128>>>(x, W_ih, W_hh, b_ih, b_hh, W_lin, b_lin, out);
}

// round 10
// speedup vs baseline: 3.0861x; 1.0806x over previous
#include <cuda_runtime.h>
#include <cstdint>

#define FULL_MASK 0xffffffffu

__device__ __forceinline__ float tanha(float x) {
    float r; asm("tanh.approx.f32 %0, %1;" : "=f"(r) : "f"(x)); return r;
}
// pack two f32 -> bf16x2 (hi arg in upper 16 bits, lo arg in lower 16)
__device__ __forceinline__ uint32_t pack_bf16(float hi, float lo) {
    uint32_t r; asm("cvt.rn.bf16x2.f32 %0, %1, %2;" : "=r"(r) : "f"(hi), "f"(lo));
    return r;
}
__device__ __forceinline__ float bf_lo(uint32_t u) { return __uint_as_float(u << 16); }
__device__ __forceinline__ float bf_hi(uint32_t u) { return __uint_as_float(u & 0xffff0000u); }

// D[16,8] += A[16,16] * B[16,8], bf16 in, f32 accum. Row-major A, col-major B.
__device__ __forceinline__ void mma16816(float4& d,
                                         uint32_t a0, uint32_t a1,
                                         uint32_t a2, uint32_t a3,
                                         uint32_t b0, uint32_t b1) {
    asm("mma.sync.aligned.m16n8k16.row.col.f32.bf16.bf16.f32 "
        "{%0,%1,%2,%3}, {%4,%5,%6,%7}, {%8,%9}, {%0,%1,%2,%3};"
        : "+f"(d.x), "+f"(d.y), "+f"(d.z), "+f"(d.w)
        : "r"(a0), "r"(a1), "r"(a2), "r"(a3), "r"(b0), "r"(b1));
}

// H=32, 4H=128 gates (g-major: n = 32*g + u), I=1, T=512, B=8192.
//
// WARP PAIR = 16 batches. Warp-even (half=0) computes D tiles with jj in
// {0,1} (units 0-15), warp-odd (half=1) jj in {2,3} (units 16-31), for all
// 4 gates. M16 rows 0-7 = batches base..+7 (D .x/.y, A slots a0/a2), rows
// 8-15 = base+8..+15 (D .z/.w, a1/a3). Lane l: gr=l/4, gc=l%4.
//
// A lane's activation outputs (h for units 8jj+2gc,+1) are exactly its own
// A-operand kfrag (kf = half); the OTHER kfrag comes from the partner warp
// via a parity double-buffered smem exchange + one named barrier per step.
//
// R10 fix vs R9: new A-words are staged in nown[][] and committed AFTER the
// jv loop — jv=1's MMAs must consume h_{t-1}, not the h_t written by jv=0.
//
// Weights Wp = PS[g]*W_hh (PS=0.5 for sigmoid gates i,f,o; 1.0 for g),
// split Wp ~= BH + BL (bf16 each); h ~= h_hi + h_lo (bf16 each).
// D = Ah*BH + Al*BH + Ah*BL per kfrag; C-init = PS*(x*W_ih + bias) fp32.
// Activations: sigmoid(u)=0.5+0.5*tanh(0.5u) (PS folded), tanh via MUFU.

__global__ void __launch_bounds__(256, 1) lstm_mma_kernel(
    const float* __restrict__ x,      // [B, 512]
    const float* __restrict__ W_ih,   // [128]
    const float* __restrict__ W_hh,   // [128, 32]
    const float* __restrict__ b_ih,   // [128]
    const float* __restrict__ b_hh,   // [128]
    const float* __restrict__ W_lin,  // [32]
    const float* __restrict__ b_lin,  // [1]
    float* __restrict__ out)          // [B]
{
    // wb4[m] = (PS*W_ih[2m], PS*(b_ih+b_hh)[2m], PS*W_ih[2m+1], PS*bias[2m+1])
    __shared__ __align__(16) float4 wb4[64];
    __shared__ __align__(16) uint2 sBL[32][32];    // [2*j+kk][lane]
    __shared__ __align__(16) float xs[4][16][36];  // [pair][batch][step] padded
    // h exchange: [pair][parity][kf][slot][lane] = {Ahi, Alo, Bhi, Blo}
    __shared__ __align__(16) uint4 exch[4][2][2][2][32];
    __shared__ float psum[4][2][16];               // epilogue partials

    const int tid  = threadIdx.x;
    const int w    = tid >> 5;
    const int l    = tid & 31;
    const int p    = w >> 1;      // warp pair (0..3)
    const int half = w & 1;       // which jj/kfrag half this warp owns
    const int gr   = l >> 2;
    const int gc   = l & 3;
    const int barid = p + 1;      // named barrier per pair

    if (tid < 64) {
        const int n0 = 2 * tid, n1 = n0 + 1;
        const float ps0 = ((n0 >> 5) == 2) ? 1.0f : 0.5f;
        const float ps1 = ((n1 >> 5) == 2) ? 1.0f : 0.5f;
        wb4[tid] = make_float4(ps0 * W_ih[n0], ps0 * (b_ih[n0] + b_hh[n0]),
                               ps1 * W_ih[n1], ps1 * (b_ih[n1] + b_hh[n1]));
    }

    // ---- B fragments for this warp's 8 tiles: own-kfrag and other-kfrag ----
    // Tile index within warp: ti = 2*g + jv (jv = local jj), jjg = 2*half+jv.
    uint2 BHown[8], BHoth[8];
    #pragma unroll
    for (int j = 0; j < 16; ++j) {
        const int jjg = j & 3, g = j >> 2;
        const int n = 8 * j + gr;
        const float ps = (g == 2) ? 1.0f : 0.5f;
        const float* wr = W_hh + n * 32;
        #pragma unroll
        for (int kk = 0; kk < 2; ++kk) {
            const int k0 = kk * 16 + 2 * gc;
            const float w00 = ps * wr[k0],     w01 = ps * wr[k0 + 1];
            const float w10 = ps * wr[k0 + 8], w11 = ps * wr[k0 + 9];
            const uint32_t b0h = pack_bf16(w01, w00);
            const uint32_t b1h = pack_bf16(w11, w10);
            if ((jjg >> 1) == half) {
                const int ti = 2 * g + (jjg & 1);
                if (kk == half) BHown[ti] = make_uint2(b0h, b1h);
                else            BHoth[ti] = make_uint2(b0h, b1h);
            }
            if (w == 0) {
                const uint32_t b0l = pack_bf16(w01 - bf_hi(b0h), w00 - bf_lo(b0h));
                const uint32_t b1l = pack_bf16(w11 - bf_hi(b1h), w10 - bf_lo(b1h));
                sBL[2 * j + kk][l] = make_uint2(b0l, b1l);
            }
        }
    }
    __syncthreads();

    const int base = (blockIdx.x * 4 + p) * 16;   // pair's first batch
    // x staging: pair-thread q loads batch q/4, steps (q%4)*8..+7 per chunk
    const int q      = half * 32 + l;
    const int xbatch = q >> 2;
    const int xoff   = (q & 3) * 8;
    const float* xb  = x + (size_t)(base + xbatch) * 512 + xoff;
    float* xw        = &xs[p][xbatch][xoff];

    // A-operand words: own kfrag (computed locally) + other kfrag (exchanged)
    // [grp(0=rows0-7,1=rows8-15)][slot][0=hi,1=lo]
    uint32_t own[2][2][2] = {{{0u,0u},{0u,0u}},{{0u,0u},{0u,0u}}};
    uint32_t oth[2][2][2] = {{{0u,0u},{0u,0u}},{{0u,0u},{0u,0u}}};

    float cc[2][2][2] = {}, hh[2][2][2] = {};   // [grp][jv][e]

    for (int t0 = 0; t0 < 512; t0 += 32) {
        const float4 v0 = *reinterpret_cast<const float4*>(xb + t0);
        const float4 v1 = *reinterpret_cast<const float4*>(xb + t0 + 4);
        *reinterpret_cast<float4*>(xw)     = v0;
        *reinterpret_cast<float4*>(xw + 4) = v1;
        asm volatile("bar.sync %0, %1;" :: "r"(barid), "r"(64) : "memory");

        #pragma unroll 2
        for (int tc = 0; tc < 32; ++tc) {
            const int par = tc & 1;
            const float xtA = xs[p][gr][tc];
            const float xtB = xs[p][gr + 8][tc];

            uint32_t nown[2][2][2];   // staged new A-words (commit after jv loop)

            #pragma unroll
            for (int jv = 0; jv < 2; ++jv) {
                const int jjg = 2 * half + jv;
                float4 d[4];
                #pragma unroll
                for (int g = 0; g < 4; ++g) {
                    const int j  = 4 * g + jjg;
                    const int ti = 2 * g + jv;
                    const float4 q4 = wb4[16 * g + 4 * jjg + gc];
                    d[g].x = fmaf(xtA, q4.x, q4.y);
                    d[g].y = fmaf(xtA, q4.z, q4.w);
                    d[g].z = fmaf(xtB, q4.x, q4.y);
                    d[g].w = fmaf(xtB, q4.z, q4.w);
                    const uint2 blo = sBL[2 * j + half][l];
                    const uint2 blx = sBL[2 * j + (half ^ 1)][l];
                    // own kfrag: Ah*BH, Al*BH, Ah*BL
                    mma16816(d[g], own[0][0][0], own[1][0][0],
                                   own[0][1][0], own[1][1][0],
                             BHown[ti].x, BHown[ti].y);
                    mma16816(d[g], own[0][0][1], own[1][0][1],
                                   own[0][1][1], own[1][1][1],
                             BHown[ti].x, BHown[ti].y);
                    mma16816(d[g], own[0][0][0], own[1][0][0],
                                   own[0][1][0], own[1][1][0],
                             blo.x, blo.y);
                    // other kfrag: same three terms
                    mma16816(d[g], oth[0][0][0], oth[1][0][0],
                                   oth[0][1][0], oth[1][1][0],
                             BHoth[ti].x, BHoth[ti].y);
                    mma16816(d[g], oth[0][0][1], oth[1][0][1],
                                   oth[0][1][1], oth[1][1][1],
                             BHoth[ti].x, BHoth[ti].y);
                    mma16816(d[g], oth[0][0][0], oth[1][0][0],
                                   oth[0][1][0], oth[1][1][0],
                             blx.x, blx.y);
                }
                // ---- activations for this jv: groups 0 (.x/.y), 1 (.z/.w) ----
                #pragma unroll
                for (int e = 0; e < 2; ++e) {
                    {   // group 0
                        const float pi = e ? d[0].y : d[0].x;
                        const float pf = e ? d[1].y : d[1].x;
                        const float pg = e ? d[2].y : d[2].x;
                        const float po = e ? d[3].y : d[3].x;
                        const float si = fmaf(0.5f, tanha(pi), 0.5f);
                        const float sf = fmaf(0.5f, tanha(pf), 0.5f);
                        const float tg = tanha(pg);
                        const float so = fmaf(0.5f, tanha(po), 0.5f);
                        cc[0][jv][e] = fmaf(sf, cc[0][jv][e], si * tg);
                        hh[0][jv][e] = so * tanha(cc[0][jv][e]);
                    }
                    {   // group 1
                        const float pi = e ? d[0].w : d[0].z;
                        const float pf = e ? d[1].w : d[1].z;
                        const float pg = e ? d[2].w : d[2].z;
                        const float po = e ? d[3].w : d[3].z;
                        const float si = fmaf(0.5f, tanha(pi), 0.5f);
                        const float sf = fmaf(0.5f, tanha(pf), 0.5f);
                        const float tg = tanha(pg);
                        const float so = fmaf(0.5f, tanha(po), 0.5f);
                        cc[1][jv][e] = fmaf(sf, cc[1][jv][e], si * tg);
                        hh[1][jv][e] = so * tanha(cc[1][jv][e]);
                    }
                }
                // pack h -> staged own-kfrag A words + publish to partner
                const uint32_t pa = pack_bf16(hh[0][jv][1], hh[0][jv][0]);
                const uint32_t la = pack_bf16(hh[0][jv][1] - bf_hi(pa),
                                              hh[0][jv][0] - bf_lo(pa));
                const uint32_t pb = pack_bf16(hh[1][jv][1], hh[1][jv][0]);
                const uint32_t lb = pack_bf16(hh[1][jv][1] - bf_hi(pb),
                                              hh[1][jv][0] - bf_lo(pb));
                nown[0][jv][0] = pa; nown[0][jv][1] = la;
                nown[1][jv][0] = pb; nown[1][jv][1] = lb;
                exch[p][par][half][jv][l] = make_uint4(pa, la, pb, lb);
            }

            // commit staged A-words (AFTER both jv tiles consumed h_{t-1})
            #pragma unroll
            for (int s = 0; s < 2; ++s) {
                own[0][s][0] = nown[0][s][0]; own[0][s][1] = nown[0][s][1];
                own[1][s][0] = nown[1][s][0]; own[1][s][1] = nown[1][s][1];
            }

            asm volatile("bar.sync %0, %1;" :: "r"(barid), "r"(64) : "memory");

            #pragma unroll
            for (int s = 0; s < 2; ++s) {
                const uint4 v = exch[p][par][half ^ 1][s][l];
                oth[0][s][0] = v.x; oth[0][s][1] = v.y;
                oth[1][s][0] = v.z; oth[1][s][1] = v.w;
            }
        }
    }

    // ---- epilogue: out[b] = dot(h, W_lin) + b_lin ----
    float vA = 0.0f, vB = 0.0f;
    #pragma unroll
    for (int jv = 0; jv < 2; ++jv) {
        const int u0 = 8 * (2 * half + jv) + 2 * gc;
        const float wl0 = W_lin[u0], wl1 = W_lin[u0 + 1];
        vA = fmaf(hh[0][jv][0], wl0, vA); vA = fmaf(hh[0][jv][1], wl1, vA);
        vB = fmaf(hh[1][jv][0], wl0, vB); vB = fmaf(hh[1][jv][1], wl1, vB);
    }
    vA += __shfl_xor_sync(FULL_MASK, vA, 1);
    vA += __shfl_xor_sync(FULL_MASK, vA, 2);
    vB += __shfl_xor_sync(FULL_MASK, vB, 1);
    vB += __shfl_xor_sync(FULL_MASK, vB, 2);
    if (gc == 0) {
        psum[p][half][gr]     = vA;
        psum[p][half][gr + 8] = vB;
    }
    asm volatile("bar.sync %0, %1;" :: "r"(barid), "r"(64) : "memory");
    if (half == 0 && gc == 0) {
        out[base + gr]     = psum[p][0][gr]     + psum[p][1][gr]     + b_lin[0];
        out[base + gr + 8] = psum[p][0][gr + 8] + psum[p][1][gr + 8] + b_lin[0];
    }
}

extern "C" void kernel_launch(void* const* d_in, const int* in_sizes, int n_in,
                              void* d_out, int out_size) {
    const float* x     = (const float*)d_in[0];
    const float* W_ih  = (const float*)d_in[1];
    const float* W_hh  = (const float*)d_in[2];
    const float* b_ih  = (const float*)d_in[3];
    const float* b_hh  = (const float*)d_in[4];
    const float* W_lin = (const float*)d_in[5];
    const float* b_lin = (const float*)d_in[6];
    float* out = (float*)d_out;

    // 8192 batches / (4 pairs * 16 batches per pair) = 128 CTAs of 256 threads.
    lstm_mma_kernel<<<128, 256>>>(x, W_ih, W_hh, b_ih, b_hh, W_lin, b_lin, out);
}

// round 11
// speedup vs baseline: 3.5343x; 1.1452x over previous
#include <cuda_runtime.h>
#include <cstdint>

#define FULL_MASK 0xffffffffu

__device__ __forceinline__ float tanha(float x) {
    float r; asm("tanh.approx.f32 %0, %1;" : "=f"(r) : "f"(x)); return r;
}
// pack two f32 -> bf16x2 (hi arg in upper 16 bits, lo arg in lower 16)
__device__ __forceinline__ uint32_t pack_bf16(float hi, float lo) {
    uint32_t r; asm("cvt.rn.bf16x2.f32 %0, %1, %2;" : "=r"(r) : "f"(hi), "f"(lo));
    return r;
}
__device__ __forceinline__ float bf_lo(uint32_t u) { return __uint_as_float(u << 16); }
__device__ __forceinline__ float bf_hi(uint32_t u) { return __uint_as_float(u & 0xffff0000u); }

// D[16,8] += A[16,16] * B[16,8], bf16 in, f32 accum. Row-major A, col-major B.
__device__ __forceinline__ void mma16816(float4& d,
                                         uint32_t a0, uint32_t a1,
                                         uint32_t a2, uint32_t a3,
                                         uint32_t b0, uint32_t b1) {
    asm("mma.sync.aligned.m16n8k16.row.col.f32.bf16.bf16.f32 "
        "{%0,%1,%2,%3}, {%4,%5,%6,%7}, {%8,%9}, {%0,%1,%2,%3};"
        : "+f"(d.x), "+f"(d.y), "+f"(d.z), "+f"(d.w)
        : "r"(a0), "r"(a1), "r"(a2), "r"(a3), "r"(b0), "r"(b1));
}

// H=32, 4H=128 gates (g-major: n = 32*g + u), I=1, T=512, B=8192.
//
// CTA (128 thr, 4 warps) = 16 batches. Warp w owns unit slice jj = w
// (units 8jj..8jj+7) across ALL 4 gates: D tiles n-cols 32g+8jj..+7.
// M16 rows 0-7 = batches base..+7 (D .x/.y), rows 8-15 = base+8..+15
// (.z/.w). Lane l: gr=l>>2, gc=l&3 -> cells (units 8jj+2gc, +1) x 2 grps.
//
// A lane's h outputs form exactly ONE A-operand word: kfrag jj>>1, slot
// jj&1. Per step each warp publishes that word (uint4: grp0hi, grp0lo,
// grp1hi, grp1lo) to a parity-double-buffered smem ring; after one
// __syncthreads every warp reads ALL FOUR slots (incl. its own) back.
// Reading own from smem removes any WAR hazard by construction.
//
// Weights Wp = PS[g]*W_hh (PS=0.5 sigmoid gates i,f,o; 1.0 for g), split
// Wp ~= BH + BL (bf16 each); h ~= hi + lo (bf16 each).
// D = Ah*BH + Al*BH + Ah*BL per kfrag (6 MMAs per gate tile, 24/warp/step).
// C-init = PS*(x*W_ih + b_ih + b_hh) in fp32 (register table).
// Activations: sigmoid(u)=0.5+0.5*tanh(0.5u) (PS folded), tanh via MUFU.

__global__ void __launch_bounds__(128, 4) lstm_mma_kernel(
    const float* __restrict__ x,      // [B, 512]
    const float* __restrict__ W_ih,   // [128]
    const float* __restrict__ W_hh,   // [128, 32]
    const float* __restrict__ b_ih,   // [128]
    const float* __restrict__ b_hh,   // [128]
    const float* __restrict__ W_lin,  // [32]
    const float* __restrict__ b_lin,  // [1]
    float* __restrict__ out)          // [B]
{
    __shared__ __align__(16) float xs[16][36];      // [batch][step] padded
    __shared__ __align__(16) uint4 exch[2][4][32];  // [parity][slot jj][lane]
    __shared__ float psum[4][16];                   // epilogue partials

    const int tid = threadIdx.x;
    const int w   = tid >> 5;      // warp = unit slice jj
    const int l   = tid & 31;
    const int jj  = w;
    const int gr  = l >> 2;
    const int gc  = l & 3;

    // ---- per-warp weight fragments in registers ----
    uint2 BH[4][2], BL[4][2];      // [gate][kfrag]
    float4 qreg[4];                // (PS*W_ih[m], PS*bias[m], ..[m+1]) per gate
    const int u0 = 8 * jj + 2 * gc;
    #pragma unroll
    for (int g = 0; g < 4; ++g) {
        const float ps = (g == 2) ? 1.0f : 0.5f;
        const int n = 8 * (4 * g + jj) + gr;       // B row for this lane
        const float* wr = W_hh + n * 32;
        #pragma unroll
        for (int kk = 0; kk < 2; ++kk) {
            const int k0 = kk * 16 + 2 * gc;
            const float w00 = ps * wr[k0],     w01 = ps * wr[k0 + 1];
            const float w10 = ps * wr[k0 + 8], w11 = ps * wr[k0 + 9];
            const uint32_t b0h = pack_bf16(w01, w00);
            const uint32_t b1h = pack_bf16(w11, w10);
            BH[g][kk] = make_uint2(b0h, b1h);
            BL[g][kk] = make_uint2(pack_bf16(w01 - bf_hi(b0h), w00 - bf_lo(b0h)),
                                   pack_bf16(w11 - bf_hi(b1h), w10 - bf_lo(b1h)));
        }
        const int m = 32 * g + u0;                 // gate rows for activations
        qreg[g] = make_float4(ps * W_ih[m],     ps * (b_ih[m]     + b_hh[m]),
                              ps * W_ih[m + 1], ps * (b_ih[m + 1] + b_hh[m + 1]));
    }

    const int base = blockIdx.x * 16;
    // x staging: thread loads batch tid/8, steps (tid%8)*4..+3 per 32-chunk
    const float* xb = x + (size_t)(base + (tid >> 3)) * 512 + (tid & 7) * 4;
    float* xw = &xs[tid >> 3][(tid & 7) * 4];

    // A-operand words [kfrag][slot] = uint4(grp0hi, grp0lo, grp1hi, grp1lo)
    uint4 Aw[2][2];
    #pragma unroll
    for (int kf = 0; kf < 2; ++kf)
        #pragma unroll
        for (int s = 0; s < 2; ++s) Aw[kf][s] = make_uint4(0u, 0u, 0u, 0u);

    float cc[2][2] = {}, hh[2][2] = {};   // [grp][e]

    for (int t0 = 0; t0 < 512; t0 += 32) {
        const float4 xv = *reinterpret_cast<const float4*>(xb + t0);
        *reinterpret_cast<float4*>(xw) = xv;
        __syncthreads();

        #pragma unroll 2
        for (int tc = 0; tc < 32; ++tc) {
            const int par = tc & 1;
            const float xtA = xs[gr][tc];
            const float xtB = xs[gr + 8][tc];

            float4 d[4];
            #pragma unroll
            for (int g = 0; g < 4; ++g) {
                d[g].x = fmaf(xtA, qreg[g].x, qreg[g].y);
                d[g].y = fmaf(xtA, qreg[g].z, qreg[g].w);
                d[g].z = fmaf(xtB, qreg[g].x, qreg[g].y);
                d[g].w = fmaf(xtB, qreg[g].z, qreg[g].w);
                #pragma unroll
                for (int kf = 0; kf < 2; ++kf) {
                    // Ah*BH, Al*BH, Ah*BL for this kfrag
                    mma16816(d[g], Aw[kf][0].x, Aw[kf][0].z,
                                   Aw[kf][1].x, Aw[kf][1].z,
                             BH[g][kf].x, BH[g][kf].y);
                    mma16816(d[g], Aw[kf][0].y, Aw[kf][0].w,
                                   Aw[kf][1].y, Aw[kf][1].w,
                             BH[g][kf].x, BH[g][kf].y);
                    mma16816(d[g], Aw[kf][0].x, Aw[kf][0].z,
                                   Aw[kf][1].x, Aw[kf][1].z,
                             BL[g][kf].x, BL[g][kf].y);
                }
            }

            // ---- activations: 2 grps x 2 elems ----
            #pragma unroll
            for (int e = 0; e < 2; ++e) {
                {   // grp 0 (.x/.y)
                    const float pi = e ? d[0].y : d[0].x;
                    const float pf = e ? d[1].y : d[1].x;
                    const float pg = e ? d[2].y : d[2].x;
                    const float po = e ? d[3].y : d[3].x;
                    const float si = fmaf(0.5f, tanha(pi), 0.5f);
                    const float sf = fmaf(0.5f, tanha(pf), 0.5f);
                    const float tg = tanha(pg);
                    const float so = fmaf(0.5f, tanha(po), 0.5f);
                    cc[0][e] = fmaf(sf, cc[0][e], si * tg);
                    hh[0][e] = so * tanha(cc[0][e]);
                }
                {   // grp 1 (.z/.w)
                    const float pi = e ? d[0].w : d[0].z;
                    const float pf = e ? d[1].w : d[1].z;
                    const float pg = e ? d[2].w : d[2].z;
                    const float po = e ? d[3].w : d[3].z;
                    const float si = fmaf(0.5f, tanha(pi), 0.5f);
                    const float sf = fmaf(0.5f, tanha(pf), 0.5f);
                    const float tg = tanha(pg);
                    const float so = fmaf(0.5f, tanha(po), 0.5f);
                    cc[1][e] = fmaf(sf, cc[1][e], si * tg);
                    hh[1][e] = so * tanha(cc[1][e]);
                }
            }

            // publish this warp's A-word (hi/lo for both grps)
            const uint32_t pa = pack_bf16(hh[0][1], hh[0][0]);
            const uint32_t la = pack_bf16(hh[0][1] - bf_hi(pa),
                                          hh[0][0] - bf_lo(pa));
            const uint32_t pb = pack_bf16(hh[1][1], hh[1][0]);
            const uint32_t lb = pack_bf16(hh[1][1] - bf_hi(pb),
                                          hh[1][0] - bf_lo(pb));
            exch[par][jj][l] = make_uint4(pa, la, pb, lb);

            __syncthreads();

            #pragma unroll
            for (int kf = 0; kf < 2; ++kf)
                #pragma unroll
                for (int s = 0; s < 2; ++s)
                    Aw[kf][s] = exch[par][2 * kf + s][l];
        }
    }

    // ---- epilogue: out[b] = dot(h, W_lin) + b_lin ----
    const float wl0 = W_lin[u0], wl1 = W_lin[u0 + 1];
    float vA = fmaf(hh[0][0], wl0, hh[0][1] * wl1);
    float vB = fmaf(hh[1][0], wl0, hh[1][1] * wl1);
    vA += __shfl_xor_sync(FULL_MASK, vA, 1);
    vA += __shfl_xor_sync(FULL_MASK, vA, 2);
    vB += __shfl_xor_sync(FULL_MASK, vB, 1);
    vB += __shfl_xor_sync(FULL_MASK, vB, 2);
    if (gc == 0) {
        psum[jj][gr]     = vA;
        psum[jj][gr + 8] = vB;
    }
    __syncthreads();
    if (w == 0 && l < 16) {
        out[base + l] = psum[0][l] + psum[1][l] + psum[2][l] + psum[3][l]
                        + b_lin[0];
    }
}

extern "C" void kernel_launch(void* const* d_in, const int* in_sizes, int n_in,
                              void* d_out, int out_size) {
    const float* x     = (const float*)d_in[0];
    const float* W_ih  = (const float*)d_in[1];
    const float* W_hh  = (const float*)d_in[2];
    const float* b_ih  = (const float*)d_in[3];
    const float* b_hh  = (const float*)d_in[4];
    const float* W_lin = (const float*)d_in[5];
    const float* b_lin = (const float*)d_in[6];
    float* out = (float*)d_out;

    // 8192 batches / 16 per CTA = 512 CTAs of 128 threads (4 warps).
    lstm_mma_kernel<<<512, 128>>>(x, W_ih, W_hh, b_ih, b_hh, W_lin, b_lin, out);
}

// round 12
// speedup vs baseline: 4.4485x; 1.2587x over previous
#include <cuda_runtime.h>
#include <cuda_fp16.h>
#include <cstdint>

#define FULL_MASK 0xffffffffu

__device__ __forceinline__ float tanha(float x) {
    float r; asm("tanh.approx.f32 %0, %1;" : "=f"(r) : "f"(x)); return r;
}
// pack two f32 -> f16x2 (hi arg in upper 16 bits, lo arg in lower 16)
__device__ __forceinline__ uint32_t pack_f16(float hi, float lo) {
    uint32_t r; asm("cvt.rn.f16x2.f32 %0, %1, %2;" : "=r"(r) : "f"(hi), "f"(lo));
    return r;
}
__device__ __forceinline__ float f16_round(float v) {
    return __half2float(__float2half_rn(v));
}

// D[16,8] += A[16,16] * B[16,8], f16 in, f32 accum. Row-major A, col-major B.
__device__ __forceinline__ void mma16816(float4& d,
                                         uint32_t a0, uint32_t a1,
                                         uint32_t a2, uint32_t a3,
                                         uint32_t b0, uint32_t b1) {
    asm("mma.sync.aligned.m16n8k16.row.col.f32.f16.f16.f32 "
        "{%0,%1,%2,%3}, {%4,%5,%6,%7}, {%8,%9}, {%0,%1,%2,%3};"
        : "+f"(d.x), "+f"(d.y), "+f"(d.z), "+f"(d.w)
        : "r"(a0), "r"(a1), "r"(a2), "r"(a3), "r"(b0), "r"(b1));
}

// H=32, 4H=128 gates (g-major: n = 32*g + u), I=1, T=512, B=8192.
//
// CTA (128 thr, 4 warps) = 16 batches. Warp w owns unit slice jj = w
// (units 8jj..8jj+7) across ALL 4 gates. M16 rows 0-7 = batches base..+7
// (D .x/.y), rows 8-15 = base+8..+15 (.z/.w). Lane l: gr=l>>2, gc=l&3.
//
// f16 precision scheme (R12): W_hh prescaled to SINGLE f16 (11 mantissa
// bits, err ~2^-11 -> ~1e-4 accumulated), h split hi+lo f16 (~22 bits).
// D = Ah*BW + Al*BW per kfrag -> 4 MMAs/gate, 16 per warp-step (was 24).
// C-init = PS*(x*W_ih + b_ih + b_hh) in fp32.
// Activations: sigmoid(u)=0.5+0.5*tanh(0.5u) (PS folded), tanh via MUFU.
//
// Per-step CTA-wide exchange: each warp publishes its A-word
// (uint4: grp0hi, grp0lo, grp1hi, grp1lo) to a parity ring; after one
// __syncthreads every warp reads all 4 slots back (incl. its own).

__global__ void __launch_bounds__(128, 4) lstm_mma_kernel(
    const float* __restrict__ x,      // [B, 512]
    const float* __restrict__ W_ih,   // [128]
    const float* __restrict__ W_hh,   // [128, 32]
    const float* __restrict__ b_ih,   // [128]
    const float* __restrict__ b_hh,   // [128]
    const float* __restrict__ W_lin,  // [32]
    const float* __restrict__ b_lin,  // [1]
    float* __restrict__ out)          // [B]
{
    __shared__ __align__(16) float xs[16][36];      // [batch][step] padded
    __shared__ __align__(16) uint4 exch[2][4][32];  // [parity][slot jj][lane]
    __shared__ float psum[4][16];                   // epilogue partials

    const int tid = threadIdx.x;
    const int w   = tid >> 5;      // warp = unit slice jj
    const int l   = tid & 31;
    const int jj  = w;
    const int gr  = l >> 2;
    const int gc  = l & 3;

    // ---- per-warp weight fragments in registers (single f16) ----
    uint2 BW[4][2];                // [gate][kfrag]
    float4 qreg[4];                // (PS*W_ih[m], PS*bias[m], ..[m+1]) per gate
    const int u0 = 8 * jj + 2 * gc;
    #pragma unroll
    for (int g = 0; g < 4; ++g) {
        const float ps = (g == 2) ? 1.0f : 0.5f;
        const int n = 8 * (4 * g + jj) + gr;       // B row for this lane
        const float* wr = W_hh + n * 32;
        #pragma unroll
        for (int kk = 0; kk < 2; ++kk) {
            const int k0 = kk * 16 + 2 * gc;
            BW[g][kk] = make_uint2(
                pack_f16(ps * wr[k0 + 1], ps * wr[k0]),
                pack_f16(ps * wr[k0 + 9], ps * wr[k0 + 8]));
        }
        const int m = 32 * g + u0;                 // gate rows for activations
        qreg[g] = make_float4(ps * W_ih[m],     ps * (b_ih[m]     + b_hh[m]),
                              ps * W_ih[m + 1], ps * (b_ih[m + 1] + b_hh[m + 1]));
    }

    const int base = blockIdx.x * 16;
    // x staging: thread loads batch tid/8, steps (tid%8)*4..+3 per 32-chunk
    const float* xb = x + (size_t)(base + (tid >> 3)) * 512 + (tid & 7) * 4;
    float* xw = &xs[tid >> 3][(tid & 7) * 4];

    // A-operand words [kfrag][slot] = uint4(grp0hi, grp0lo, grp1hi, grp1lo)
    uint4 Aw[2][2];
    #pragma unroll
    for (int kf = 0; kf < 2; ++kf)
        #pragma unroll
        for (int s = 0; s < 2; ++s) Aw[kf][s] = make_uint4(0u, 0u, 0u, 0u);

    float cc[2][2] = {}, hh[2][2] = {};   // [grp][e]

    for (int t0 = 0; t0 < 512; t0 += 32) {
        const float4 xv = *reinterpret_cast<const float4*>(xb + t0);
        *reinterpret_cast<float4*>(xw) = xv;
        __syncthreads();

        #pragma unroll 2
        for (int tc = 0; tc < 32; ++tc) {
            const int par = tc & 1;
            const float xtA = xs[gr][tc];
            const float xtB = xs[gr + 8][tc];

            float4 d[4];
            #pragma unroll
            for (int g = 0; g < 4; ++g) {
                d[g].x = fmaf(xtA, qreg[g].x, qreg[g].y);
                d[g].y = fmaf(xtA, qreg[g].z, qreg[g].w);
                d[g].z = fmaf(xtB, qreg[g].x, qreg[g].y);
                d[g].w = fmaf(xtB, qreg[g].z, qreg[g].w);
                #pragma unroll
                for (int kf = 0; kf < 2; ++kf) {
                    // Ah*BW + Al*BW for this kfrag
                    mma16816(d[g], Aw[kf][0].x, Aw[kf][0].z,
                                   Aw[kf][1].x, Aw[kf][1].z,
                             BW[g][kf].x, BW[g][kf].y);
                    mma16816(d[g], Aw[kf][0].y, Aw[kf][0].w,
                                   Aw[kf][1].y, Aw[kf][1].w,
                             BW[g][kf].x, BW[g][kf].y);
                }
            }

            // ---- activations: 2 grps x 2 elems ----
            #pragma unroll
            for (int e = 0; e < 2; ++e) {
                {   // grp 0 (.x/.y)
                    const float pi = e ? d[0].y : d[0].x;
                    const float pf = e ? d[1].y : d[1].x;
                    const float pg = e ? d[2].y : d[2].x;
                    const float po = e ? d[3].y : d[3].x;
                    const float si = fmaf(0.5f, tanha(pi), 0.5f);
                    const float sf = fmaf(0.5f, tanha(pf), 0.5f);
                    const float tg = tanha(pg);
                    const float so = fmaf(0.5f, tanha(po), 0.5f);
                    cc[0][e] = fmaf(sf, cc[0][e], si * tg);
                    hh[0][e] = so * tanha(cc[0][e]);
                }
                {   // grp 1 (.z/.w)
                    const float pi = e ? d[0].w : d[0].z;
                    const float pf = e ? d[1].w : d[1].z;
                    const float pg = e ? d[2].w : d[2].z;
                    const float po = e ? d[3].w : d[3].z;
                    const float si = fmaf(0.5f, tanha(pi), 0.5f);
                    const float sf = fmaf(0.5f, tanha(pf), 0.5f);
                    const float tg = tanha(pg);
                    const float so = fmaf(0.5f, tanha(po), 0.5f);
                    cc[1][e] = fmaf(sf, cc[1][e], si * tg);
                    hh[1][e] = so * tanha(cc[1][e]);
                }
            }

            // publish this warp's A-word: h split hi+lo (f16)
            const float h00h = f16_round(hh[0][0]);
            const float h01h = f16_round(hh[0][1]);
            const float h10h = f16_round(hh[1][0]);
            const float h11h = f16_round(hh[1][1]);
            const uint32_t pa = pack_f16(h01h, h00h);
            const uint32_t la = pack_f16(hh[0][1] - h01h, hh[0][0] - h00h);
            const uint32_t pb = pack_f16(h11h, h10h);
            const uint32_t lb = pack_f16(hh[1][1] - h11h, hh[1][0] - h10h);
            exch[par][jj][l] = make_uint4(pa, la, pb, lb);

            __syncthreads();

            #pragma unroll
            for (int kf = 0; kf < 2; ++kf)
                #pragma unroll
                for (int s = 0; s < 2; ++s)
                    Aw[kf][s] = exch[par][2 * kf + s][l];
        }
    }

    // ---- epilogue: out[b] = dot(h, W_lin) + b_lin ----
    const float wl0 = W_lin[u0], wl1 = W_lin[u0 + 1];
    float vA = fmaf(hh[0][0], wl0, hh[0][1] * wl1);
    float vB = fmaf(hh[1][0], wl0, hh[1][1] * wl1);
    vA += __shfl_xor_sync(FULL_MASK, vA, 1);
    vA += __shfl_xor_sync(FULL_MASK, vA, 2);
    vB += __shfl_xor_sync(FULL_MASK, vB, 1);
    vB += __shfl_xor_sync(FULL_MASK, vB, 2);
    if (gc == 0) {
        psum[jj][gr]     = vA;
        psum[jj][gr + 8] = vB;
    }
    __syncthreads();
    if (w == 0 && l < 16) {
        out[base + l] = psum[0][l] + psum[1][l] + psum[2][l] + psum[3][l]
                        + b_lin[0];
    }
}

extern "C" void kernel_launch(void* const* d_in, const int* in_sizes, int n_in,
                              void* d_out, int out_size) {
    const float* x     = (const float*)d_in[0];
    const float* W_ih  = (const float*)d_in[1];
    const float* W_hh  = (const float*)d_in[2];
    const float* b_ih  = (const float*)d_in[3];
    const float* b_hh  = (const float*)d_in[4];
    const float* W_lin = (const float*)d_in[5];
    const float* b_lin = (const float*)d_in[6];
    float* out = (float*)d_out;

    // 8192 batches / 16 per CTA = 512 CTAs of 128 threads (4 warps).
    lstm_mma_kernel<<<512, 128>>>(x, W_ih, W_hh, b_ih, b_hh, W_lin, b_lin, out);
}